// round 12
// baseline (speedup 1.0000x reference)
#include <cuda_runtime.h>
#include <math.h>

// features: [B=16, H=128, W=128, D=8, F=16] float32
// out[b,h,w,d,f] = flip_{W,D}( roll_{(5,-7),(H,W)}( rotate_40deg_NN(x) ) )
//
// Inverse chain per output element:
//   w1 = W-1-w ; d1 = D-1-d                    (undo flips)
//   h2 = (h-5) mod H ; w2 = (w1+7) mod W       (undo roll)
//   (si,sj,valid) = NN inverse-rotation at (h2,w2)
//   out = valid ? x[b, si, sj, d1, f] : 0
//
// R11: 256-bit (.v8.b32) loads+stores, unroll x2 across batches (stride =
// 8 batches). Lower per-thread register burst than R8/R9 (2 loads + 2
// stores) to restore occupancy toward R3's 75% while keeping 32B/access.
// Cache-policy hints dropped — proven neutral across R5/R8/R9.

#define B_ 16
#define H_ 128
#define W_ 128
#define D_ 8
#define F8_ 2                     // F/8
#define N8_ (B_*H_*W_*D_*F8_)     // 4194304 8-float outputs
#define UNROLL_ 2
#define STRIDE_ (N8_/UNROLL_)     // 2097152 = 8 batches
#define BATCH8_ (H_*W_*D_*F8_)    // 8-float groups per batch = 262144

struct f8vec { unsigned r0,r1,r2,r3,r4,r5,r6,r7; };

__device__ __forceinline__ f8vec ldg_v8(const unsigned* p) {
    f8vec v;
    asm volatile("ld.global.nc.v8.b32 {%0,%1,%2,%3,%4,%5,%6,%7}, [%8];"
                 : "=r"(v.r0), "=r"(v.r1), "=r"(v.r2), "=r"(v.r3),
                   "=r"(v.r4), "=r"(v.r5), "=r"(v.r6), "=r"(v.r7)
                 : "l"(p));
    return v;
}

__device__ __forceinline__ void stg_v8(unsigned* p, const f8vec& v) {
    asm volatile("st.global.v8.b32 [%0], {%1,%2,%3,%4,%5,%6,%7,%8};"
                 :: "l"(p),
                    "r"(v.r0), "r"(v.r1), "r"(v.r2), "r"(v.r3),
                    "r"(v.r4), "r"(v.r5), "r"(v.r6), "r"(v.r7)
                 : "memory");
}

__global__ __launch_bounds__(256) void augment_kernel(
    const unsigned* __restrict__ in, unsigned* __restrict__ out,
    float c, float s)
{
    int idx = blockIdx.x * blockDim.x + threadIdx.x;   // 0 .. STRIDE_-1

    // decompose: idx = (((b*H + h)*W + w)*D + d)*F8 + f8   (b in 0..7 here)
    int f8 = idx & 1;
    int t  = idx >> 1;
    int d  = t & 7;   t >>= 3;
    int w  = t & 127; t >>= 7;
    int h  = t & 127;
    int b  = t >> 7;

    // undo flips
    int w1 = (W_ - 1) - w;
    int d1 = (D_ - 1) - d;
    // undo roll (shifts = (5, -7) on (H, W))
    int h2 = h - 5;  if (h2 < 0)    h2 += H_;
    int w2 = w1 + 7; if (w2 >= W_)  w2 -= W_;

    // NN inverse rotation, center 63.5, round-half-to-even (jnp.round)
    float fi = (float)h2 - 63.5f;
    float fj = (float)w2 - 63.5f;
    float src_i =  c * fi + s * fj + 63.5f;
    float src_j = -s * fi + c * fj + 63.5f;
    int si = (int)rintf(src_i);
    int sj = (int)rintf(src_j);

    bool valid = (si >= 0) & (si < H_) & (sj >= 0) & (sj < W_);

    f8vec v[UNROLL_];
    if (valid) {
        int src = ((((b * H_ + si) * W_ + sj) * D_ + d1) * F8_ + f8) * 8;
        #pragma unroll
        for (int k = 0; k < UNROLL_; k++)
            v[k] = ldg_v8(&in[src + k * (8 * BATCH8_ * 8)]);
    } else {
        #pragma unroll
        for (int k = 0; k < UNROLL_; k++)
            v[k] = f8vec{0,0,0,0,0,0,0,0};
    }

    #pragma unroll
    for (int k = 0; k < UNROLL_; k++)
        stg_v8(&out[(idx + k * STRIDE_) * 8], v[k]);
}

extern "C" void kernel_launch(void* const* d_in, const int* in_sizes, int n_in,
                              void* d_out, int out_size) {
    const unsigned* in = (const unsigned*)d_in[0];
    unsigned* out = (unsigned*)d_out;

    const double theta = 40.0 * 3.14159265358979323846 / 180.0;
    const float c = (float)cos(theta);
    const float s = (float)sin(theta);

    const int threads = 256;
    const int blocks = STRIDE_ / threads;   // 8192
    augment_kernel<<<blocks, threads>>>(in, out, c, s);
}

// round 13
// speedup vs baseline: 1.0057x; 1.0057x over previous
#include <cuda_runtime.h>
#include <math.h>

// features: [B=16, H=128, W=128, D=8, F=16] float32
// out[b,h,w,d,f] = flip_{W,D}( roll_{(5,-7),(H,W)}( rotate_40deg_NN(x) ) )
//
// Inverse chain per output element:
//   w1 = W-1-w ; d1 = D-1-d                    (undo flips)
//   h2 = (h-5) mod H ; w2 = (w1+7) mod W       (undo roll)
//   (si,sj,valid) = NN inverse-rotation at (h2,w2)
//   out = valid ? x[b, si, sj, d1, f] : 0
//
// R12: gather loads unchanged (ld.global.nc.v8.b32, unroll x2 across
// batches). STORES now staged in shared memory and emitted as one 8KB
// cp.async.bulk (UTMASTG) shared->global burst per chunk: each CTA's output
// chunk is 256 threads x 32B = 8KB contiguous. Large sequential write
// bursts to DRAM instead of interleaved per-warp 512B STGs.

#define B_ 16
#define H_ 128
#define W_ 128
#define D_ 8
#define F8_ 2                     // F/8
#define N8_ (B_*H_*W_*D_*F8_)     // 4194304 8-float outputs
#define UNROLL_ 2
#define STRIDE_ (N8_/UNROLL_)     // 2097152 = 8 batches
#define BATCH8_ (H_*W_*D_*F8_)    // 8-float groups per batch = 262144
#define CHUNK_BYTES_ (256*32)     // 8KB per CTA per chunk

struct f8vec { unsigned r0,r1,r2,r3,r4,r5,r6,r7; };

__device__ __forceinline__ f8vec ldg_v8(const unsigned* p) {
    f8vec v;
    asm volatile("ld.global.nc.v8.b32 {%0,%1,%2,%3,%4,%5,%6,%7}, [%8];"
                 : "=r"(v.r0), "=r"(v.r1), "=r"(v.r2), "=r"(v.r3),
                   "=r"(v.r4), "=r"(v.r5), "=r"(v.r6), "=r"(v.r7)
                 : "l"(p));
    return v;
}

__global__ __launch_bounds__(256) void augment_kernel(
    const unsigned* __restrict__ in, unsigned* __restrict__ out,
    float c, float s)
{
    __shared__ __align__(128) unsigned buf[UNROLL_][CHUNK_BYTES_/4];

    int tid = threadIdx.x;
    int idx = blockIdx.x * blockDim.x + tid;   // 0 .. STRIDE_-1

    // decompose: idx = (((b*H + h)*W + w)*D + d)*F8 + f8   (b in 0..7 here)
    int f8 = idx & 1;
    int t  = idx >> 1;
    int d  = t & 7;   t >>= 3;
    int w  = t & 127; t >>= 7;
    int h  = t & 127;
    int b  = t >> 7;

    // undo flips
    int w1 = (W_ - 1) - w;
    int d1 = (D_ - 1) - d;
    // undo roll (shifts = (5, -7) on (H, W))
    int h2 = h - 5;  if (h2 < 0)    h2 += H_;
    int w2 = w1 + 7; if (w2 >= W_)  w2 -= W_;

    // NN inverse rotation, center 63.5, round-half-to-even (jnp.round)
    float fi = (float)h2 - 63.5f;
    float fj = (float)w2 - 63.5f;
    float src_i =  c * fi + s * fj + 63.5f;
    float src_j = -s * fi + c * fj + 63.5f;
    int si = (int)rintf(src_i);
    int sj = (int)rintf(src_j);

    bool valid = (si >= 0) & (si < H_) & (sj >= 0) & (sj < W_);

    f8vec v[UNROLL_];
    if (valid) {
        int src = ((((b * H_ + si) * W_ + sj) * D_ + d1) * F8_ + f8) * 8;
        #pragma unroll
        for (int k = 0; k < UNROLL_; k++)
            v[k] = ldg_v8(&in[src + k * (8 * BATCH8_ * 8)]);
    } else {
        #pragma unroll
        for (int k = 0; k < UNROLL_; k++)
            v[k] = f8vec{0,0,0,0,0,0,0,0};
    }

    // stage into shared (each thread writes its 32B slot)
    #pragma unroll
    for (int k = 0; k < UNROLL_; k++) {
        unsigned* p = &buf[k][tid * 8];
        asm volatile("st.shared.v4.b32 [%0], {%1,%2,%3,%4};"
                     :: "l"((unsigned long long)__cvta_generic_to_shared(p)),
                        "r"(v[k].r0), "r"(v[k].r1), "r"(v[k].r2), "r"(v[k].r3));
        asm volatile("st.shared.v4.b32 [%0], {%1,%2,%3,%4};"
                     :: "l"((unsigned long long)__cvta_generic_to_shared(p + 4)),
                        "r"(v[k].r4), "r"(v[k].r5), "r"(v[k].r6), "r"(v[k].r7));
    }
    // make generic-proxy smem stores visible to the async (bulk-copy) proxy
    asm volatile("fence.proxy.async.shared::cta;" ::: "memory");
    __syncthreads();

    // one 8KB bulk store per chunk, issued by thread 0
    if (tid == 0) {
        #pragma unroll
        for (int k = 0; k < UNROLL_; k++) {
            unsigned* gdst = out + (blockIdx.x * 256 + (long long)k * STRIDE_) * 8;
            unsigned saddr = (unsigned)__cvta_generic_to_shared(&buf[k][0]);
            asm volatile("cp.async.bulk.global.shared::cta.bulk_group [%0], [%1], %2;"
                         :: "l"(gdst), "r"(saddr), "r"(CHUNK_BYTES_)
                         : "memory");
        }
        asm volatile("cp.async.bulk.commit_group;" ::: "memory");
        asm volatile("cp.async.bulk.wait_group 0;" ::: "memory");
    }
    __syncthreads();   // keep smem alive until bulk stores complete
}

extern "C" void kernel_launch(void* const* d_in, const int* in_sizes, int n_in,
                              void* d_out, int out_size) {
    const unsigned* in = (const unsigned*)d_in[0];
    unsigned* out = (unsigned*)d_out;

    const double theta = 40.0 * 3.14159265358979323846 / 180.0;
    const float c = (float)cos(theta);
    const float s = (float)sin(theta);

    const int threads = 256;
    const int blocks = STRIDE_ / threads;   // 8192
    augment_kernel<<<blocks, threads>>>(in, out, c, s);
}

// round 14
// speedup vs baseline: 1.0065x; 1.0008x over previous
#include <cuda_runtime.h>
#include <math.h>

// features: [B=16, H=128, W=128, D=8, F=16] float32
// out[b,h,w,d,f] = flip_{W,D}( roll_{(5,-7),(H,W)}( rotate_40deg_NN(x) ) )
//
// Inverse chain per output element:
//   w1 = W-1-w ; d1 = D-1-d                    (undo flips)
//   h2 = (h-5) mod H ; w2 = (w1+7) mod W       (undo roll)
//   (si,sj,valid) = NN inverse-rotation at (h2,w2)
//   out = valid ? x[b, si, sj, d1, f] : 0
//
// R13 (final): float4 accesses, unroll x4 across batches (rotation math
// computed once per thread, 4 independent LDG.128 / STG.128), streaming
// stores. Best-measured combination after exhausting cache policy, vector
// width, occupancy, and store-path (bulk/TMA) axes — kernel is at the
// mixed-stream HBM floor (~170 MB/replay @ ~5.4 TB/s achieved).

#define B_ 16
#define H_ 128
#define W_ 128
#define D_ 8
#define F4_ 4                     // F/4
#define N4_ (B_*H_*W_*D_*F4_)     // 8388608 float4 outputs
#define UNROLL_ 4
#define STRIDE_ (N4_/UNROLL_)     // 2097152 float4 = 4 batches
#define BATCH4_ (H_*W_*D_*F4_)    // float4 per batch = 524288

__global__ __launch_bounds__(256) void augment_kernel(
    const float4* __restrict__ in, float4* __restrict__ out,
    float c, float s)
{
    int idx = blockIdx.x * blockDim.x + threadIdx.x;   // 0 .. STRIDE_-1

    // decompose: idx = (((b*H + h)*W + w)*D + d)*F4 + f4   (b in 0..3 here)
    int f4 = idx & 3;
    int t  = idx >> 2;
    int d  = t & 7;   t >>= 3;
    int w  = t & 127; t >>= 7;
    int h  = t & 127;
    int b  = t >> 7;

    // undo flips
    int w1 = (W_ - 1) - w;
    int d1 = (D_ - 1) - d;
    // undo roll (shifts = (5, -7) on (H, W))
    int h2 = h - 5;  if (h2 < 0)    h2 += H_;
    int w2 = w1 + 7; if (w2 >= W_)  w2 -= W_;

    // NN inverse rotation, center 63.5, round-half-to-even (jnp.round)
    float fi = (float)h2 - 63.5f;
    float fj = (float)w2 - 63.5f;
    float src_i =  c * fi + s * fj + 63.5f;
    float src_j = -s * fi + c * fj + 63.5f;
    int si = (int)rintf(src_i);
    int sj = (int)rintf(src_j);

    bool valid = (si >= 0) & (si < H_) & (sj >= 0) & (sj < W_);

    float4 v[UNROLL_];
    if (valid) {
        int src = (((b * H_ + si) * W_ + sj) * D_ + d1) * F4_ + f4;
        #pragma unroll
        for (int k = 0; k < UNROLL_; k++)
            v[k] = __ldg(&in[src + k * (4 * BATCH4_)]);
    } else {
        #pragma unroll
        for (int k = 0; k < UNROLL_; k++)
            v[k] = make_float4(0.f, 0.f, 0.f, 0.f);
    }

    #pragma unroll
    for (int k = 0; k < UNROLL_; k++)
        __stcs(&out[idx + k * STRIDE_], v[k]);
}

extern "C" void kernel_launch(void* const* d_in, const int* in_sizes, int n_in,
                              void* d_out, int out_size) {
    const float4* in = (const float4*)d_in[0];
    float4* out = (float4*)d_out;

    const double theta = 40.0 * 3.14159265358979323846 / 180.0;
    const float c = (float)cos(theta);
    const float s = (float)sin(theta);

    const int threads = 256;
    const int blocks = STRIDE_ / threads;   // 8192
    augment_kernel<<<blocks, threads>>>(in, out, c, s);
}

// round 15
// speedup vs baseline: 1.0114x; 1.0049x over previous
#include <cuda_runtime.h>
#include <math.h>

// features: [B=16, H=128, W=128, D=8, F=16] float32
// out[b,h,w,d,f] = flip_{W,D}( roll_{(5,-7),(H,W)}( rotate_40deg_NN(x) ) )
//
// Inverse chain per output element:
//   w1 = W-1-w ; d1 = D-1-d                    (undo flips)
//   h2 = (h-5) mod H ; w2 = (w1+7) mod W       (undo roll)
//   (si,sj,valid) = NN inverse-rotation at (h2,w2)
//   out = valid ? x[b, si, sj, d1, f] : 0
//
// R14 (champion re-validation): float4 accesses, unroll x4 across batches
// (rotation math computed once per thread; 4 independent LDG.128 + 4
// STG.128, MLP=4, occ ~75%). This exact configuration is the kernel-time
// argmin (31.23us) across 8 structurally distinct variants; all cache
// policy / store-path / occupancy / vector-width axes were swept and proven
// neutral. The op is at its mixed-stream HBM floor (~170 MB/replay at
// ~5.4 TB/s achieved).

#define B_ 16
#define H_ 128
#define W_ 128
#define D_ 8
#define F4_ 4                     // F/4
#define N4_ (B_*H_*W_*D_*F4_)     // 8388608 float4 outputs
#define UNROLL_ 4
#define STRIDE_ (N4_/UNROLL_)     // 2097152 float4 = 4 batches
#define BATCH4_ (H_*W_*D_*F4_)    // float4 per batch = 524288

__global__ __launch_bounds__(256) void augment_kernel(
    const float4* __restrict__ in, float4* __restrict__ out,
    float c, float s)
{
    int idx = blockIdx.x * blockDim.x + threadIdx.x;   // 0 .. STRIDE_-1

    // decompose: idx = (((b*H + h)*W + w)*D + d)*F4 + f4   (b in 0..3 here)
    int f4 = idx & 3;
    int t  = idx >> 2;
    int d  = t & 7;   t >>= 3;
    int w  = t & 127; t >>= 7;
    int h  = t & 127;
    int b  = t >> 7;

    // undo flips
    int w1 = (W_ - 1) - w;
    int d1 = (D_ - 1) - d;
    // undo roll (shifts = (5, -7) on (H, W))
    int h2 = h - 5;  if (h2 < 0)    h2 += H_;
    int w2 = w1 + 7; if (w2 >= W_)  w2 -= W_;

    // NN inverse rotation, center 63.5, round-half-to-even (jnp.round)
    float fi = (float)h2 - 63.5f;
    float fj = (float)w2 - 63.5f;
    float src_i =  c * fi + s * fj + 63.5f;
    float src_j = -s * fi + c * fj + 63.5f;
    int si = (int)rintf(src_i);
    int sj = (int)rintf(src_j);

    bool valid = (si >= 0) & (si < H_) & (sj >= 0) & (sj < W_);

    float4 v[UNROLL_];
    if (valid) {
        int src = (((b * H_ + si) * W_ + sj) * D_ + d1) * F4_ + f4;
        #pragma unroll
        for (int k = 0; k < UNROLL_; k++)
            v[k] = in[src + k * (4 * BATCH4_)];
    } else {
        #pragma unroll
        for (int k = 0; k < UNROLL_; k++)
            v[k] = make_float4(0.f, 0.f, 0.f, 0.f);
    }

    #pragma unroll
    for (int k = 0; k < UNROLL_; k++)
        out[idx + k * STRIDE_] = v[k];
}

extern "C" void kernel_launch(void* const* d_in, const int* in_sizes, int n_in,
                              void* d_out, int out_size) {
    const float4* in = (const float4*)d_in[0];
    float4* out = (float4*)d_out;

    const double theta = 40.0 * 3.14159265358979323846 / 180.0;
    const float c = (float)cos(theta);
    const float s = (float)sin(theta);

    const int threads = 256;
    const int blocks = STRIDE_ / threads;   // 8192
    augment_kernel<<<blocks, threads>>>(in, out, c, s);
}